// round 2
// baseline (speedup 1.0000x reference)
#include <cuda_runtime.h>
#include <math.h>

#define MAXN 100000
#define MAXE 1600000
#define F 32

// Scratch (device globals: no allocations allowed)
__device__ float    g_deg [MAXN];
__device__ float    g_dinv[MAXN];
__device__ float    g_hA  [MAXN * F];   // linear output of current layer (gather source)
__device__ float    g_hB  [MAXN * F];   // aggregation accumulator (scatter dest)
__device__ unsigned g_max [F];          // max-pool accumulator (float bits, nonneg)

// ---------------------------------------------------------------- init
__global__ void k_init(int n) {
    int i = blockIdx.x * blockDim.x + threadIdx.x;
    if (i < n) g_deg[i] = 1.0f;          // self loop
    if (i < F) g_max[i] = 0u;            // relu outputs are >= 0
}

// ---------------------------------------------------------------- degree
__global__ void k_deg(const int* __restrict__ ei, int E) {
    int e = blockIdx.x * blockDim.x + threadIdx.x;
    if (e < E) atomicAdd(&g_deg[ei[E + e]], 1.0f);
}

__global__ void k_dinv(int n) {
    int i = blockIdx.x * blockDim.x + threadIdx.x;
    if (i < n) g_dinv[i] = rsqrtf(g_deg[i]);
}

// ---------------------------------------------------------------- layer1 dense: hA = x@W1, hB = hA*dinv^2 (self loop)
__global__ void k_xw1(const float* __restrict__ x, const float* __restrict__ W1, int n) {
    __shared__ float Ws[8 * F];
    int t = threadIdx.x;
    if (t < 8 * F) Ws[t] = W1[t];
    __syncthreads();
    int lane = t & 31, w = t >> 5;
    int node = blockIdx.x * 8 + w;
    if (node >= n) return;
    float xv = (lane < 8) ? x[node * 8 + lane] : 0.f;
    float acc = 0.f;
#pragma unroll
    for (int k = 0; k < 8; k++)
        acc = fmaf(__shfl_sync(0xffffffffu, xv, k), Ws[k * F + lane], acc);
    float d = g_dinv[node];
    g_hA[node * F + lane] = acc;
    g_hB[node * F + lane] = acc * d * d;
}

// ---------------------------------------------------------------- edge scatter: hB[dst] += hA[src]*dinv[src]*dinv[dst]
__global__ void k_scatter(const int* __restrict__ ei, int E) {
    int lane = threadIdx.x & 31, w = threadIdx.x >> 5;
    int e = blockIdx.x * 8 + w;
    if (e >= E) return;
    int s = ei[e];
    int d = ei[E + e];
    float norm = g_dinv[s] * g_dinv[d];
    atomicAdd(&g_hB[d * F + lane], g_hA[s * F + lane] * norm);
}

// ------------------------------------------------- between layers: r = relu(hB+b1); hA = r@W2; hB = hA*dinv^2
__global__ void k_mid(const float* __restrict__ b1, const float* __restrict__ W2, int n) {
    __shared__ float Ws[F * F];
    int t = threadIdx.x;
    for (int i = t; i < F * F; i += blockDim.x) Ws[i] = W2[i];
    __syncthreads();
    int lane = t & 31, w = t >> 5;
    int node = blockIdx.x * 8 + w;
    if (node >= n) return;
    float r = fmaxf(g_hB[node * F + lane] + b1[lane], 0.f);
    float acc = 0.f;
#pragma unroll
    for (int k = 0; k < F; k++)
        acc = fmaf(__shfl_sync(0xffffffffu, r, k), Ws[k * F + lane], acc);
    float d = g_dinv[node];
    g_hA[node * F + lane] = acc;
    g_hB[node * F + lane] = acc * d * d;
}

// ---------------------------------------------------------------- relu(hB+b2) then global max pool
__global__ void k_maxpool(const float* __restrict__ b2, int n) {
    __shared__ float sm[8][F];
    int lane = threadIdx.x & 31, w = threadIdx.x >> 5;
    float bias = b2[lane];
    float m = 0.f;
    for (int node = blockIdx.x * 8 + w; node < n; node += gridDim.x * 8) {
        float v = fmaxf(g_hB[node * F + lane] + bias, 0.f);
        m = fmaxf(m, v);
    }
    sm[w][lane] = m;
    __syncthreads();
    if (w == 0) {
        float mm = sm[0][lane];
#pragma unroll
        for (int i = 1; i < 8; i++) mm = fmaxf(mm, sm[i][lane]);
        atomicMax(&g_max[lane], __float_as_uint(mm));  // safe: values >= 0
    }
}

// ---------------------------------------------------------------- FC head + log_softmax (tiny)
__global__ void k_head(const float* __restrict__ fcW, const float* __restrict__ fcb,
                       float* __restrict__ out) {
    __shared__ float g[F];
    __shared__ float logits[5];
    int t = threadIdx.x;
    if (t < F) g[t] = __uint_as_float(g_max[t]);
    __syncthreads();
    if (t < 5) {
        float acc = fcb[t];
#pragma unroll
        for (int k = 0; k < F; k++) acc = fmaf(g[k], fcW[k * 5 + t], acc);
        logits[t] = acc;
    }
    __syncthreads();
    if (t == 0) {
        float m = logits[0];
#pragma unroll
        for (int c = 1; c < 5; c++) m = fmaxf(m, logits[c]);
        float s = 0.f;
#pragma unroll
        for (int c = 0; c < 5; c++) s += __expf(logits[c] - m);
        float lse = logf(s);
#pragma unroll
        for (int c = 0; c < 5; c++) out[c] = logits[c] - m - lse;
    }
}

// ================================================================ launch
extern "C" void kernel_launch(void* const* d_in, const int* in_sizes, int n_in,
                              void* d_out, int out_size) {
    const float* x   = (const float*)d_in[0];
    const int*   ei  = (const int*)d_in[1];
    const float* W1  = (const float*)d_in[2];
    const float* b1  = (const float*)d_in[3];
    const float* W2  = (const float*)d_in[4];
    const float* b2  = (const float*)d_in[5];
    const float* fcW = (const float*)d_in[6];
    const float* fcb = (const float*)d_in[7];
    float*       out = (float*)d_out;

    int n = in_sizes[0] / 8;       // 100000
    int E = in_sizes[1] / 2;       // 1600000

    const int TB = 256;
    int gridN   = (n + TB - 1) / TB;
    int gridE   = (E + TB - 1) / TB;
    int gridNW  = (n + 7) / 8;     // warp-per-node
    int gridEW  = (E + 7) / 8;     // warp-per-edge

    k_init   <<<gridN, TB>>>(n);
    k_deg    <<<gridE, TB>>>(ei, E);
    k_dinv   <<<gridN, TB>>>(n);
    k_xw1    <<<gridNW, TB>>>(x, W1, n);
    k_scatter<<<gridEW, TB>>>(ei, E);
    k_mid    <<<gridNW, TB>>>(b1, W2, n);
    k_scatter<<<gridEW, TB>>>(ei, E);
    k_maxpool<<<512, TB>>>(b2, n);
    k_head   <<<1, 32>>>(fcW, fcb, out);
}

// round 3
// speedup vs baseline: 1.8377x; 1.8377x over previous
#include <cuda_runtime.h>
#include <math.h>

#define MAXN 100000
#define MAXE 1600000
#define F 32

__device__ float    g_deg [MAXN];
__device__ float    g_dinv[MAXN];
__device__ float    g_hA  [MAXN * F];   // pre-scaled (by dinv[src]) gather source
__device__ float    g_hB  [MAXN * F];   // aggregation accumulator
__device__ unsigned g_max [F];

// ---------------------------------------------------------------- init
__global__ void k_init(int n) {
    int i = blockIdx.x * blockDim.x + threadIdx.x;
    if (i < n) g_deg[i] = 1.0f;          // self loop
    if (i < F) g_max[i] = 0u;            // relu outputs >= 0
}

// ---------------------------------------------------------------- degree (4 edges/thread, vector index load)
__global__ void k_deg(const int* __restrict__ ei, int E) {
    int t = blockIdx.x * blockDim.x + threadIdx.x;
    int e = t * 4;
    if (e >= E) return;
    int4 d4 = *(const int4*)&ei[E + e];
    atomicAdd(&g_deg[d4.x], 1.0f);
    atomicAdd(&g_deg[d4.y], 1.0f);
    atomicAdd(&g_deg[d4.z], 1.0f);
    atomicAdd(&g_deg[d4.w], 1.0f);
}

__global__ void k_dinv(int n) {
    int i = blockIdx.x * blockDim.x + threadIdx.x;
    if (i < n) g_dinv[i] = rsqrtf(g_deg[i]);
}

// ------------------------------------------- layer1 dense: hA = (x@W1)*dinv, hB = (x@W1)*dinv^2 (self loop)
__global__ void k_xw1(const float* __restrict__ x, const float* __restrict__ W1, int n) {
    __shared__ float Ws[8 * F];
    int t = threadIdx.x;
    if (t < 8 * F) Ws[t] = W1[t];
    __syncthreads();
    int lane = t & 31, w = t >> 5;
    int node = blockIdx.x * 8 + w;
    if (node >= n) return;
    float xv = (lane < 8) ? x[node * 8 + lane] : 0.f;
    float acc = 0.f;
#pragma unroll
    for (int k = 0; k < 8; k++)
        acc = fmaf(__shfl_sync(0xffffffffu, xv, k), Ws[k * F + lane], acc);
    float d = g_dinv[node];
    g_hA[node * F + lane] = acc * d;          // pre-scaled by dinv[src]
    g_hB[node * F + lane] = acc * d * d;      // self-loop contribution
}

// ------------------------- edge scatter: hB[dst] += hA[src]*dinv[dst]   (8 lanes x float4 per edge)
__global__ void k_scatter(const int* __restrict__ ei, int E) {
    int lane = threadIdx.x & 31;
    int g    = lane >> 3;                     // edge slot within warp (0..3)
    int sl   = lane & 7;                      // float4 slot within row (0..7)
    int e = ((blockIdx.x * blockDim.x + threadIdx.x) >> 5) * 4 + g;
    if (e >= E) return;
    int s = ei[e];
    int d = ei[E + e];
    float nd = g_dinv[d];
    float4 v = *(const float4*)&g_hA[s * F + sl * 4];
    v.x *= nd; v.y *= nd; v.z *= nd; v.w *= nd;
    asm volatile("red.global.add.v4.f32 [%0], {%1, %2, %3, %4};"
                 :: "l"(&g_hB[d * F + sl * 4]),
                    "f"(v.x), "f"(v.y), "f"(v.z), "f"(v.w) : "memory");
}

// ------------------- between layers: r = relu(hB+b1); hA = (r@W2)*dinv; hB = (r@W2)*dinv^2
__global__ void k_mid(const float* __restrict__ b1, const float* __restrict__ W2, int n) {
    __shared__ float Ws[F * F];
    int t = threadIdx.x;
    for (int i = t; i < F * F; i += blockDim.x) Ws[i] = W2[i];
    __syncthreads();
    int lane = t & 31, w = t >> 5;
    int node = blockIdx.x * 8 + w;
    if (node >= n) return;
    float r = fmaxf(g_hB[node * F + lane] + b1[lane], 0.f);
    float acc = 0.f;
#pragma unroll
    for (int k = 0; k < F; k++)
        acc = fmaf(__shfl_sync(0xffffffffu, r, k), Ws[k * F + lane], acc);
    float d = g_dinv[node];
    g_hA[node * F + lane] = acc * d;
    g_hB[node * F + lane] = acc * d * d;
}

// ---------------------------------------------------------------- relu(hB+b2) then global max pool
__global__ void k_maxpool(const float* __restrict__ b2, int n) {
    __shared__ float sm[8][F];
    int lane = threadIdx.x & 31, w = threadIdx.x >> 5;
    float bias = b2[lane];
    float m = 0.f;
    for (int node = blockIdx.x * 8 + w; node < n; node += gridDim.x * 8) {
        float v = fmaxf(g_hB[node * F + lane] + bias, 0.f);
        m = fmaxf(m, v);
    }
    sm[w][lane] = m;
    __syncthreads();
    if (w == 0) {
        float mm = sm[0][lane];
#pragma unroll
        for (int i = 1; i < 8; i++) mm = fmaxf(mm, sm[i][lane]);
        atomicMax(&g_max[lane], __float_as_uint(mm));
    }
}

// ---------------------------------------------------------------- FC head + log_softmax
__global__ void k_head(const float* __restrict__ fcW, const float* __restrict__ fcb,
                       float* __restrict__ out) {
    __shared__ float g[F];
    __shared__ float logits[5];
    int t = threadIdx.x;
    if (t < F) g[t] = __uint_as_float(g_max[t]);
    __syncthreads();
    if (t < 5) {
        float acc = fcb[t];
#pragma unroll
        for (int k = 0; k < F; k++) acc = fmaf(g[k], fcW[k * 5 + t], acc);
        logits[t] = acc;
    }
    __syncthreads();
    if (t == 0) {
        float m = logits[0];
#pragma unroll
        for (int c = 1; c < 5; c++) m = fmaxf(m, logits[c]);
        float s = 0.f;
#pragma unroll
        for (int c = 0; c < 5; c++) s += __expf(logits[c] - m);
        float lse = logf(s);
#pragma unroll
        for (int c = 0; c < 5; c++) out[c] = logits[c] - m - lse;
    }
}

// ================================================================ launch
extern "C" void kernel_launch(void* const* d_in, const int* in_sizes, int n_in,
                              void* d_out, int out_size) {
    const float* x   = (const float*)d_in[0];
    const int*   ei  = (const int*)d_in[1];
    const float* W1  = (const float*)d_in[2];
    const float* b1  = (const float*)d_in[3];
    const float* W2  = (const float*)d_in[4];
    const float* b2  = (const float*)d_in[5];
    const float* fcW = (const float*)d_in[6];
    const float* fcb = (const float*)d_in[7];
    float*       out = (float*)d_out;

    int n = in_sizes[0] / 8;       // 100000
    int E = in_sizes[1] / 2;       // 1600000

    const int TB = 256;
    int gridN  = (n + TB - 1) / TB;
    int gridE4 = (E / 4 + TB - 1) / TB;           // 4 edges/thread (deg)
    int gridNW = (n + 7) / 8;                     // warp-per-node
    int gridEV = (E + 31) / 32;                   // 32 edges/block (8 warps x 4)

    k_init   <<<gridN, TB>>>(n);
    k_deg    <<<gridE4, TB>>>(ei, E);
    k_dinv   <<<gridN, TB>>>(n);
    k_xw1    <<<gridNW, TB>>>(x, W1, n);
    k_scatter<<<gridEV, TB>>>(ei, E);
    k_mid    <<<gridNW, TB>>>(b1, W2, n);
    k_scatter<<<gridEV, TB>>>(ei, E);
    k_maxpool<<<512, TB>>>(b2, n);
    k_head   <<<1, 32>>>(fcW, fcb, out);
}

// round 4
// speedup vs baseline: 2.0536x; 1.1175x over previous
#include <cuda_runtime.h>
#include <math.h>

#define MAXN 100000
#define MAXE 1600000
#define F 32

__device__ float    g_deg [MAXN];
__device__ float    g_dinv[MAXN];
__device__ float    g_hA  [MAXN * F];   // gather source, pre-scaled by dinv[src]
__device__ float    g_hB  [MAXN * F];   // unscaled aggregation accumulator (post-scaled by dinv[dst] later)
__device__ unsigned g_max [F];

// ---------------------------------------------------------------- init
__global__ void k_init(int n) {
    int i = blockIdx.x * blockDim.x + threadIdx.x;
    if (i < n) g_deg[i] = 1.0f;          // self loop
    if (i < F) g_max[i] = 0u;            // relu outputs >= 0
}

// ---------------------------------------------------------------- degree (4 edges/thread)
__global__ void k_deg(const int* __restrict__ ei, int E) {
    int t = blockIdx.x * blockDim.x + threadIdx.x;
    int e = t * 4;
    if (e >= E) return;
    int4 d4 = *(const int4*)&ei[E + e];
    atomicAdd(&g_deg[d4.x], 1.0f);
    atomicAdd(&g_deg[d4.y], 1.0f);
    atomicAdd(&g_deg[d4.z], 1.0f);
    atomicAdd(&g_deg[d4.w], 1.0f);
}

__global__ void k_dinv(int n) {
    int i = blockIdx.x * blockDim.x + threadIdx.x;
    if (i < n) g_dinv[i] = rsqrtf(g_deg[i]);
}

// ---------------- layer1 dense (thread-per-node): hA = hB = (x@W1)*dinv
__global__ void k_xw1(const float* __restrict__ x, const float* __restrict__ W1, int n) {
    __shared__ float Ws[8 * F];
    int t = threadIdx.x;
    if (t < 8 * F) Ws[t] = W1[t];
    __syncthreads();
    int node = blockIdx.x * blockDim.x + t;
    if (node >= n) return;
    float4 x0 = *(const float4*)&x[node * 8];
    float4 x1 = *(const float4*)&x[node * 8 + 4];
    float xv[8] = {x0.x, x0.y, x0.z, x0.w, x1.x, x1.y, x1.z, x1.w};
    float acc[F];
#pragma unroll
    for (int j = 0; j < F; j++) acc[j] = 0.f;
#pragma unroll
    for (int k = 0; k < 8; k++)
#pragma unroll
        for (int j = 0; j < F; j++)
            acc[j] = fmaf(xv[k], Ws[k * F + j], acc[j]);
    float d = g_dinv[node];
    float4* pa = (float4*)&g_hA[node * F];
    float4* pb = (float4*)&g_hB[node * F];
#pragma unroll
    for (int q = 0; q < 8; q++) {
        float4 v = make_float4(acc[q*4]*d, acc[q*4+1]*d, acc[q*4+2]*d, acc[q*4+3]*d);
        pa[q] = v;
        pb[q] = v;   // self-loop term (post-scale by dinv[dst] applied downstream)
    }
}

// ---------------- edge scatter: hB[dst] += hA[src]   (8 lanes x float4 per edge, no scaling)
__global__ void k_scatter(const int* __restrict__ ei, int E) {
    int lane = threadIdx.x & 31;
    int g    = lane >> 3;                     // edge slot within warp (0..3)
    int sl   = lane & 7;                      // float4 slot within row (0..7)
    int e = ((blockIdx.x * blockDim.x + threadIdx.x) >> 5) * 4 + g;
    if (e >= E) return;
    int s = ei[e];
    int d = ei[E + e];
    float4 v = *(const float4*)&g_hA[s * F + sl * 4];
    asm volatile("red.global.add.v4.f32 [%0], {%1, %2, %3, %4};"
                 :: "l"(&g_hB[d * F + sl * 4]),
                    "f"(v.x), "f"(v.y), "f"(v.z), "f"(v.w) : "memory");
}

// -------- between layers (thread-per-node): r = relu(dinv*hB + b1); hA = hB = (r@W2)*dinv
__global__ void k_mid(const float* __restrict__ b1, const float* __restrict__ W2, int n) {
    __shared__ float Ws[F * F];
    __shared__ float bs[F];
    int t = threadIdx.x;
    for (int i = t; i < F * F; i += blockDim.x) Ws[i] = W2[i];
    if (t < F) bs[t] = b1[t];
    __syncthreads();
    int node = blockIdx.x * blockDim.x + t;
    if (node >= n) return;
    float d = g_dinv[node];
    const float4* hb = (const float4*)&g_hB[node * F];
    float acc[F];
#pragma unroll
    for (int j = 0; j < F; j++) acc[j] = 0.f;
#pragma unroll
    for (int q = 0; q < 8; q++) {
        float4 hv = hb[q];
        float r0 = fmaxf(fmaf(d, hv.x, bs[q*4+0]), 0.f);
        float r1 = fmaxf(fmaf(d, hv.y, bs[q*4+1]), 0.f);
        float r2 = fmaxf(fmaf(d, hv.z, bs[q*4+2]), 0.f);
        float r3 = fmaxf(fmaf(d, hv.w, bs[q*4+3]), 0.f);
#pragma unroll
        for (int j = 0; j < F; j++) {
            acc[j] = fmaf(r0, Ws[(q*4+0) * F + j], acc[j]);
            acc[j] = fmaf(r1, Ws[(q*4+1) * F + j], acc[j]);
            acc[j] = fmaf(r2, Ws[(q*4+2) * F + j], acc[j]);
            acc[j] = fmaf(r3, Ws[(q*4+3) * F + j], acc[j]);
        }
    }
    float4* pa = (float4*)&g_hA[node * F];
    float4* pb = (float4*)&g_hB[node * F];
#pragma unroll
    for (int q = 0; q < 8; q++) {
        float4 v = make_float4(acc[q*4]*d, acc[q*4+1]*d, acc[q*4+2]*d, acc[q*4+3]*d);
        pa[q] = v;
        pb[q] = v;
    }
}

// ---------------------------------------------------------------- relu(dinv*hB+b2) then global max pool
__global__ void k_maxpool(const float* __restrict__ b2, int n) {
    __shared__ float sm[8][F];
    int lane = threadIdx.x & 31, w = threadIdx.x >> 5;
    float bias = b2[lane];
    float m = 0.f;
    for (int node = blockIdx.x * 8 + w; node < n; node += gridDim.x * 8) {
        float d = g_dinv[node];
        float v = fmaxf(fmaf(d, g_hB[node * F + lane], bias), 0.f);
        m = fmaxf(m, v);
    }
    sm[w][lane] = m;
    __syncthreads();
    if (w == 0) {
        float mm = sm[0][lane];
#pragma unroll
        for (int i = 1; i < 8; i++) mm = fmaxf(mm, sm[i][lane]);
        atomicMax(&g_max[lane], __float_as_uint(mm));
    }
}

// ---------------------------------------------------------------- FC head + log_softmax
__global__ void k_head(const float* __restrict__ fcW, const float* __restrict__ fcb,
                       float* __restrict__ out) {
    __shared__ float g[F];
    __shared__ float logits[5];
    int t = threadIdx.x;
    if (t < F) g[t] = __uint_as_float(g_max[t]);
    __syncthreads();
    if (t < 5) {
        float acc = fcb[t];
#pragma unroll
        for (int k = 0; k < F; k++) acc = fmaf(g[k], fcW[k * 5 + t], acc);
        logits[t] = acc;
    }
    __syncthreads();
    if (t == 0) {
        float m = logits[0];
#pragma unroll
        for (int c = 1; c < 5; c++) m = fmaxf(m, logits[c]);
        float s = 0.f;
#pragma unroll
        for (int c = 0; c < 5; c++) s += __expf(logits[c] - m);
        float lse = logf(s);
#pragma unroll
        for (int c = 0; c < 5; c++) out[c] = logits[c] - m - lse;
    }
}

// ================================================================ launch
extern "C" void kernel_launch(void* const* d_in, const int* in_sizes, int n_in,
                              void* d_out, int out_size) {
    const float* x   = (const float*)d_in[0];
    const int*   ei  = (const int*)d_in[1];
    const float* W1  = (const float*)d_in[2];
    const float* b1  = (const float*)d_in[3];
    const float* W2  = (const float*)d_in[4];
    const float* b2  = (const float*)d_in[5];
    const float* fcW = (const float*)d_in[6];
    const float* fcb = (const float*)d_in[7];
    float*       out = (float*)d_out;

    int n = in_sizes[0] / 8;       // 100000
    int E = in_sizes[1] / 2;       // 1600000

    const int TB = 256;
    int gridN  = (n + TB - 1) / TB;
    int gridE4 = (E / 4 + TB - 1) / TB;
    int gridEV = (E + 31) / 32;                   // 32 edges/block

    k_init   <<<gridN, TB>>>(n);
    k_deg    <<<gridE4, TB>>>(ei, E);
    k_dinv   <<<gridN, TB>>>(n);
    k_xw1    <<<gridN, TB>>>(x, W1, n);
    k_scatter<<<gridEV, TB>>>(ei, E);
    k_mid    <<<gridN, TB>>>(b1, W2, n);
    k_scatter<<<gridEV, TB>>>(ei, E);
    k_maxpool<<<512, TB>>>(b2, n);
    k_head   <<<1, 32>>>(fcW, fcb, out);
}

// round 7
// speedup vs baseline: 2.3029x; 1.1214x over previous
#include <cuda_runtime.h>
#include <math.h>

#define MAXN 100000
#define MAXE 1600000
#define F 32
#define SCAN_B 1024

__device__ int      g_cnt [MAXN];       // in-degree (real edges)
__device__ int      g_row [MAXN + 1];   // CSR row offsets
__device__ int      g_cur [MAXN];       // fill cursors
__device__ int      g_csr [MAXE];       // CSR src indices
__device__ int      g_bsum[(MAXN + SCAN_B - 1) / SCAN_B];
__device__ float    g_dinv[MAXN];
__device__ float    g_hA  [MAXN * F];   // gather source, pre-scaled by dinv[src]
__device__ float    g_hB  [MAXN * F];   // aggregate output (post-scaled by dinv[dst] downstream)
__device__ unsigned g_max [F];

// ---------------------------------------------------------------- init
__global__ void k_init(int n) {
    int i = blockIdx.x * blockDim.x + threadIdx.x;
    if (i < n) g_cnt[i] = 0;
    if (i < F) g_max[i] = 0u;
}

// ---------------------------------------------------------------- in-degree count (4 edges/thread)
__global__ void k_count(const int* __restrict__ ei, int E) {
    int e = (blockIdx.x * blockDim.x + threadIdx.x) * 4;
    if (e >= E) return;
    int4 d4 = *(const int4*)&ei[E + e];
    atomicAdd(&g_cnt[d4.x], 1);
    atomicAdd(&g_cnt[d4.y], 1);
    atomicAdd(&g_cnt[d4.z], 1);
    atomicAdd(&g_cnt[d4.w], 1);
}

// ---------------------------------------------------------------- scan pass 1: per-block exclusive scan
__global__ void k_scan1(int n) {
    __shared__ int sm[SCAN_B];
    int tid = threadIdx.x;
    int i = blockIdx.x * SCAN_B + tid;
    int v = (i < n) ? g_cnt[i] : 0;
    sm[tid] = v;
    __syncthreads();
#pragma unroll
    for (int off = 1; off < SCAN_B; off <<= 1) {
        int t = (tid >= off) ? sm[tid - off] : 0;
        __syncthreads();
        sm[tid] += t;
        __syncthreads();
    }
    if (i < n) g_row[i] = sm[tid] - v;            // exclusive
    if (tid == SCAN_B - 1) g_bsum[blockIdx.x] = sm[tid];
}

// ---------------------------------------------------------------- scan pass 2: scan block sums (tiny)
__global__ void k_scan2(int nb) {
    if (threadIdx.x == 0) {
        int run = 0;
        for (int b = 0; b < nb; b++) { int t = g_bsum[b]; g_bsum[b] = run; run += t; }
    }
}

// ---------------------------- scan pass 3: add offsets, set cursors, compute dinv (deg = cnt+1)
__global__ void k_scan3(int n, int E) {
    int i = blockIdx.x * blockDim.x + threadIdx.x;
    if (i < n) {
        int r = g_row[i] + g_bsum[i / SCAN_B];
        g_row[i] = r;
        g_cur[i] = r;
        g_dinv[i] = rsqrtf((float)(g_cnt[i] + 1));
    }
    if (i == 0) g_row[n] = E;
}

// ---------------------------------------------------------------- CSR fill (4 edges/thread)
__global__ void k_fill(const int* __restrict__ ei, int E) {
    int e = (blockIdx.x * blockDim.x + threadIdx.x) * 4;
    if (e >= E) return;
    int4 s4 = *(const int4*)&ei[e];
    int4 d4 = *(const int4*)&ei[E + e];
    g_csr[atomicAdd(&g_cur[d4.x], 1)] = s4.x;
    g_csr[atomicAdd(&g_cur[d4.y], 1)] = s4.y;
    g_csr[atomicAdd(&g_cur[d4.z], 1)] = s4.z;
    g_csr[atomicAdd(&g_cur[d4.w], 1)] = s4.w;
}

// ---------------- layer1 dense (thread-per-node): hA = (x@W1)*dinv
__global__ void k_xw1(const float* __restrict__ x, const float* __restrict__ W1, int n) {
    __shared__ float Ws[8 * F];
    int t = threadIdx.x;
    for (int i = t; i < 8 * F; i += blockDim.x) Ws[i] = W1[i];   // FIXED: strided load
    __syncthreads();
    int node = blockIdx.x * blockDim.x + t;
    if (node >= n) return;
    float4 x0 = *(const float4*)&x[node * 8];
    float4 x1 = *(const float4*)&x[node * 8 + 4];
    float xv[8] = {x0.x, x0.y, x0.z, x0.w, x1.x, x1.y, x1.z, x1.w};
    float acc[F];
#pragma unroll
    for (int j = 0; j < F; j++) acc[j] = 0.f;
#pragma unroll
    for (int k = 0; k < 8; k++)
#pragma unroll
        for (int j = 0; j < F; j++)
            acc[j] = fmaf(xv[k], Ws[k * F + j], acc[j]);
    float d = g_dinv[node];
    float4* pa = (float4*)&g_hA[node * F];
#pragma unroll
    for (int q = 0; q < 8; q++)
        pa[q] = make_float4(acc[q*4]*d, acc[q*4+1]*d, acc[q*4+2]*d, acc[q*4+3]*d);
}

// ---------------- aggregate (warp-per-node): hB[v] = hA[v] + sum_{s in N(v)} hA[s]
__global__ void k_agg(int n) {
    int lane = threadIdx.x & 31, w = threadIdx.x >> 5;
    int node = blockIdx.x * 8 + w;
    if (node >= n) return;
    int g  = lane >> 3;          // edge group 0..3
    int sl = lane & 7;           // float4 slot 0..7
    int start = g_row[node], end = g_row[node + 1];
    float4 acc = make_float4(0.f, 0.f, 0.f, 0.f);
    for (int base = start + g; base < end; base += 4) {
        int s = g_csr[base];
        float4 v = *(const float4*)&g_hA[s * F + sl * 4];
        acc.x += v.x; acc.y += v.y; acc.z += v.z; acc.w += v.w;
    }
#pragma unroll
    for (int off = 16; off >= 8; off >>= 1) {
        acc.x += __shfl_xor_sync(0xffffffffu, acc.x, off);
        acc.y += __shfl_xor_sync(0xffffffffu, acc.y, off);
        acc.z += __shfl_xor_sync(0xffffffffu, acc.z, off);
        acc.w += __shfl_xor_sync(0xffffffffu, acc.w, off);
    }
    if (lane < 8) {
        float4 sv = *(const float4*)&g_hA[node * F + lane * 4];
        *(float4*)&g_hB[node * F + lane * 4] =
            make_float4(acc.x + sv.x, acc.y + sv.y, acc.z + sv.z, acc.w + sv.w);
    }
}

// -------- between layers (thread-per-node): r = relu(dinv*hB + b1); hA = (r@W2)*dinv
__global__ void k_mid(const float* __restrict__ b1, const float* __restrict__ W2, int n) {
    __shared__ float Ws[F * F];
    __shared__ float bs[F];
    int t = threadIdx.x;
    for (int i = t; i < F * F; i += blockDim.x) Ws[i] = W2[i];
    if (t < F) bs[t] = b1[t];
    __syncthreads();
    int node = blockIdx.x * blockDim.x + t;
    if (node >= n) return;
    float d = g_dinv[node];
    const float4* hb = (const float4*)&g_hB[node * F];
    float acc[F];
#pragma unroll
    for (int j = 0; j < F; j++) acc[j] = 0.f;
#pragma unroll
    for (int q = 0; q < 8; q++) {
        float4 hv = hb[q];
        float r0 = fmaxf(fmaf(d, hv.x, bs[q*4+0]), 0.f);
        float r1 = fmaxf(fmaf(d, hv.y, bs[q*4+1]), 0.f);
        float r2 = fmaxf(fmaf(d, hv.z, bs[q*4+2]), 0.f);
        float r3 = fmaxf(fmaf(d, hv.w, bs[q*4+3]), 0.f);
#pragma unroll
        for (int j = 0; j < F; j++) {
            acc[j] = fmaf(r0, Ws[(q*4+0) * F + j], acc[j]);
            acc[j] = fmaf(r1, Ws[(q*4+1) * F + j], acc[j]);
            acc[j] = fmaf(r2, Ws[(q*4+2) * F + j], acc[j]);
            acc[j] = fmaf(r3, Ws[(q*4+3) * F + j], acc[j]);
        }
    }
    float4* pa = (float4*)&g_hA[node * F];
#pragma unroll
    for (int q = 0; q < 8; q++)
        pa[q] = make_float4(acc[q*4]*d, acc[q*4+1]*d, acc[q*4+2]*d, acc[q*4+3]*d);
}

// ---------------------------------------------------------------- relu(dinv*hB+b2) then global max pool
__global__ void k_maxpool(const float* __restrict__ b2, int n) {
    __shared__ float sm[8][F];
    int lane = threadIdx.x & 31, w = threadIdx.x >> 5;
    float bias = b2[lane];
    float m = 0.f;
    for (int node = blockIdx.x * 8 + w; node < n; node += gridDim.x * 8) {
        float d = g_dinv[node];
        float v = fmaxf(fmaf(d, g_hB[node * F + lane], bias), 0.f);
        m = fmaxf(m, v);
    }
    sm[w][lane] = m;
    __syncthreads();
    if (w == 0) {
        float mm = sm[0][lane];
#pragma unroll
        for (int i = 1; i < 8; i++) mm = fmaxf(mm, sm[i][lane]);
        atomicMax(&g_max[lane], __float_as_uint(mm));
    }
}

// ---------------------------------------------------------------- FC head + log_softmax
__global__ void k_head(const float* __restrict__ fcW, const float* __restrict__ fcb,
                       float* __restrict__ out) {
    __shared__ float g[F];
    __shared__ float logits[5];
    int t = threadIdx.x;
    if (t < F) g[t] = __uint_as_float(g_max[t]);
    __syncthreads();
    if (t < 5) {
        float acc = fcb[t];
#pragma unroll
        for (int k = 0; k < F; k++) acc = fmaf(g[k], fcW[k * 5 + t], acc);
        logits[t] = acc;
    }
    __syncthreads();
    if (t == 0) {
        float m = logits[0];
#pragma unroll
        for (int c = 1; c < 5; c++) m = fmaxf(m, logits[c]);
        float s = 0.f;
#pragma unroll
        for (int c = 0; c < 5; c++) s += __expf(logits[c] - m);
        float lse = logf(s);
#pragma unroll
        for (int c = 0; c < 5; c++) out[c] = logits[c] - m - lse;
    }
}

// ================================================================ launch
extern "C" void kernel_launch(void* const* d_in, const int* in_sizes, int n_in,
                              void* d_out, int out_size) {
    const float* x   = (const float*)d_in[0];
    const int*   ei  = (const int*)d_in[1];
    const float* W1  = (const float*)d_in[2];
    const float* b1  = (const float*)d_in[3];
    const float* W2  = (const float*)d_in[4];
    const float* b2  = (const float*)d_in[5];
    const float* fcW = (const float*)d_in[6];
    const float* fcb = (const float*)d_in[7];
    float*       out = (float*)d_out;

    int n = in_sizes[0] / 8;       // 100000
    int E = in_sizes[1] / 2;       // 1600000

    const int TB = 256;
    int gridN   = (n + TB - 1) / TB;
    int gridE4  = (E / 4 + TB - 1) / TB;
    int gridNW  = (n + 7) / 8;                 // warp-per-node
    int nScanB  = (n + SCAN_B - 1) / SCAN_B;
    int gridD   = (n + 127) / 128;             // dense kernels, TB=128

    k_init   <<<gridN, TB>>>(n);
    k_count  <<<gridE4, TB>>>(ei, E);
    k_scan1  <<<nScanB, SCAN_B>>>(n);
    k_scan2  <<<1, 32>>>(nScanB);
    k_scan3  <<<gridN, TB>>>(n, E);
    k_fill   <<<gridE4, TB>>>(ei, E);
    k_xw1    <<<gridD, 128>>>(x, W1, n);
    k_agg    <<<gridNW, TB>>>(n);
    k_mid    <<<gridD, 128>>>(b1, W2, n);
    k_agg    <<<gridNW, TB>>>(n);
    k_maxpool<<<512, TB>>>(b2, n);
    k_head   <<<1, 32>>>(fcW, fcb, out);
}